// round 6
// baseline (speedup 1.0000x reference)
#include <cuda_runtime.h>
#include <math_constants.h>
#include <math.h>
#include <cstdint>

#define TOKENS 16384
#define HIDDEN 7168
#define NEXP   256
#define TOPK   8
#define BK     16
#define NCH    (HIDDEN / BK)   // 448
#define TAU    1e-4f

// SMEM per stage: Adup [16][256] f32 = 16KB | B [16][256] f32 = 16KB
#define ST_BYTES 32768
#define OFF_A    0
#define OFF_B    16384
#define SMEM_TOTAL (2 * ST_BYTES)

__device__ float g_logits[(size_t)TOKENS * NEXP];
__device__ float g_Bt[(size_t)NEXP * HIDDEN];    // chunk-blocked [ch][k][n]
__device__ int   g_nflag;
__device__ int   g_flagged[TOKENS];

#define CPA16(dst, src) \
    asm volatile("cp.async.cg.shared.global [%0], [%1], 16;" \
                 :: "r"(dst), "l"(src) : "memory")

// ---------------------------------------------------------------------------
// Kernel 0: transpose W [n][k] -> g_Bt [chunk][k][n] (SMEM-image layout).
// ---------------------------------------------------------------------------
__global__ __launch_bounds__(256)
void convert_b_kernel(const float* __restrict__ W) {
    if (blockIdx.x == 0 && threadIdx.x == 0) g_nflag = 0;   // per-launch reset

    const int ch = blockIdx.x;
    const int n  = threadIdx.x;
    const float* src = W + (size_t)n * HIDDEN + ch * BK;
    float* dst = g_Bt + (size_t)ch * (BK * NEXP);
    #pragma unroll
    for (int j = 0; j < 4; j++) {
        float4 v = *(const float4*)(src + 4 * j);
        dst[(4 * j + 0) * NEXP + n] = v.x;
        dst[(4 * j + 1) * NEXP + n] = v.y;
        dst[(4 * j + 2) * NEXP + n] = v.z;
        dst[(4 * j + 3) * NEXP + n] = v.w;
    }
}

// ---------------------------------------------------------------------------
// Kernel 1: fp32 SGEMM via packed fma.rn.f32x2.
// CTA = 128 tokens x 256 experts, 256 threads, per-thread tile 8M x 16N
// (64 f32x2 accumulators). A stored pair-duplicated in SMEM so a-fragments
// load as {a,a} via ld.shared.v2.u64 — no packing in the inner loop.
// ---------------------------------------------------------------------------
__global__ __launch_bounds__(256, 1)
void gemm_f32x2(const float* __restrict__ A)
{
    extern __shared__ char smem[];
    uint32_t sb;
    asm("{ .reg .u64 t; cvta.to.shared.u64 t, %1; cvt.u32.u64 %0, t; }"
        : "=r"(sb) : "l"((void*)smem));

    const int tid  = threadIdx.x;
    const int tx   = tid & 15;          // N: cols tx*16 .. +16
    const int ty   = tid >> 4;          // M: rows ty*8 .. +8
    const int bm   = blockIdx.x * 128;

    // A loader: 2 threads per row, 8 k's each
    const int arow  = tid >> 1;
    const int apart = tid & 1;
    const float* Agp = A + (size_t)(bm + arow) * HIDDEN + apart * 8;

    unsigned long long acc[8][8];
    #pragma unroll
    for (int i = 0; i < 8; i++)
        #pragma unroll
        for (int j = 0; j < 8; j++) acc[i][j] = 0ULL;

#define LOAD_B_ASYNC(nc, st) do {                                              \
        const char* __s = (const char*)(g_Bt + (size_t)(nc) * (BK * NEXP))     \
                          + tid * 64;                                          \
        uint32_t __d = sb + (st) * ST_BYTES + OFF_B + tid * 64;                \
        CPA16(__d,      __s);                                                  \
        CPA16(__d + 16, __s + 16);                                             \
        CPA16(__d + 32, __s + 32);                                             \
        CPA16(__d + 48, __s + 48);                                             \
        asm volatile("cp.async.commit_group;" ::: "memory");                   \
    } while (0)

    // store one float4 (4 consecutive k) duplicated into Adup[k][2*row]
#define STS_DUP(ab, kbase, v) do {                                             \
        asm volatile("st.shared.v2.f32 [%0], {%1,%1};"                         \
                     :: "r"((ab) + ((kbase) + 0) * 1024), "f"((v).x) : "memory"); \
        asm volatile("st.shared.v2.f32 [%0], {%1,%1};"                         \
                     :: "r"((ab) + ((kbase) + 1) * 1024), "f"((v).y) : "memory"); \
        asm volatile("st.shared.v2.f32 [%0], {%1,%1};"                         \
                     :: "r"((ab) + ((kbase) + 2) * 1024), "f"((v).z) : "memory"); \
        asm volatile("st.shared.v2.f32 [%0], {%1,%1};"                         \
                     :: "r"((ab) + ((kbase) + 3) * 1024), "f"((v).w) : "memory"); \
    } while (0)

#define STORE_A(st, v0, v1) do {                                               \
        const uint32_t __ab = sb + (st) * ST_BYTES + OFF_A + arow * 8;         \
        STS_DUP(__ab, apart * 8 + 0, v0);                                      \
        STS_DUP(__ab, apart * 8 + 4, v1);                                      \
    } while (0)

    // ---- prologue: stage 0 ----
    {
        LOAD_B_ASYNC(0, 0);
        float4 v0 = __ldg((const float4*)Agp);
        float4 v1 = __ldg((const float4*)(Agp + 4));
        STORE_A(0, v0, v1);
        asm volatile("cp.async.wait_group 0;" ::: "memory");
        __syncthreads();
    }

    // ---- main loop over 448 chunks of K=16 ----
    for (int c = 0; c < NCH; c++) {
        const int s   = c & 1;
        const bool np = (c + 1 < NCH);
        float4 v0, v1;
        if (np) {
            LOAD_B_ASYNC(c + 1, s ^ 1);
            v0 = __ldg((const float4*)(Agp + (size_t)(c + 1) * BK));
            v1 = __ldg((const float4*)(Agp + (size_t)(c + 1) * BK + 4));
        }

        const uint32_t base = sb + s * ST_BYTES;
        const uint32_t abase0 = base + OFF_A + ty * 64;   // pairs for rows ty*8..
        const uint32_t bbase0 = base + OFF_B + tx * 64;   // floats tx*16..

        #pragma unroll
        for (int k = 0; k < BK; k++) {
            unsigned long long a2[8], b2[8];
            const uint32_t ab = abase0 + k * 1024;
            const uint32_t bb = bbase0 + k * 1024;
            #pragma unroll
            for (int q = 0; q < 4; q++) {
                asm("ld.shared.v2.u64 {%0,%1}, [%2];"
                    : "=l"(a2[2 * q]), "=l"(a2[2 * q + 1]) : "r"(ab + q * 16));
            }
            #pragma unroll
            for (int q = 0; q < 4; q++) {
                asm("ld.shared.v2.u64 {%0,%1}, [%2];"
                    : "=l"(b2[2 * q]), "=l"(b2[2 * q + 1]) : "r"(bb + q * 16));
            }
            #pragma unroll
            for (int i = 0; i < 8; i++)
                #pragma unroll
                for (int j = 0; j < 8; j++)
                    asm("fma.rn.f32x2 %0, %1, %2, %0;"
                        : "+l"(acc[i][j]) : "l"(a2[i]), "l"(b2[j]));
        }

        if (np) {
            STORE_A(s ^ 1, v0, v1);
            asm volatile("cp.async.wait_group 0;" ::: "memory");
        }
        __syncthreads();
    }

    // ---- epilogue: 8 rows x 16 consecutive floats each ----
    #pragma unroll
    for (int i = 0; i < 8; i++) {
        float* out = g_logits + (size_t)(bm + ty * 8 + i) * NEXP + tx * 16;
        #pragma unroll
        for (int q = 0; q < 4; q++) {
            *(ulonglong2*)(out + 4 * q) =
                make_ulonglong2(acc[i][2 * q], acc[i][2 * q + 1]);
        }
    }
}

// ---------------------------------------------------------------------------
// route_one: reference-exact routing for one token (validated R4/R5).
// ---------------------------------------------------------------------------
__device__ __forceinline__ void route_one(const float* __restrict__ row,
                                          const float* __restrict__ bias,
                                          float* __restrict__ out,
                                          int write_idx, int token, int lane,
                                          int do_flag)
{
    const unsigned FULL = 0xffffffffu;

    float4 l0 = *(const float4*)(row + lane * 8);
    float4 l1 = *(const float4*)(row + lane * 8 + 4);
    float4 b0 = *(const float4*)(bias + lane * 8);
    float4 b1 = *(const float4*)(bias + lane * 8 + 4);

    float lv[8] = {l0.x, l0.y, l0.z, l0.w, l1.x, l1.y, l1.z, l1.w};
    float bb[8] = {b0.x, b0.y, b0.z, b0.w, b1.x, b1.y, b1.z, b1.w};
    float sc[8], s4[8];
    #pragma unroll
    for (int i = 0; i < 8; i++) {
        float s = 1.0f / (1.0f + expf(-lv[i]));
        sc[i] = s;
        s4[i] = s + bb[i];
    }

    float m1 = -CUDART_INF_F, m2 = -CUDART_INF_F, m3 = -CUDART_INF_F;
    #pragma unroll
    for (int i = 0; i < 8; i++) {
        float v = s4[i];
        if (v > m1)      { m3 = m2; m2 = m1; m1 = v; }
        else if (v > m2) { m3 = m2; m2 = v; }
        else if (v > m3) { m3 = v; }
    }
    #pragma unroll
    for (int d = 1; d <= 2; d <<= 1) {
        float o1 = __shfl_xor_sync(FULL, m1, d);
        float o2 = __shfl_xor_sync(FULL, m2, d);
        float o3 = __shfl_xor_sync(FULL, m3, d);
        float mn1 = fminf(m1, o1);
        float mx2 = fmaxf(m2, o2);
        float n1 = fmaxf(m1, o1);
        float n2 = fmaxf(mn1, mx2);
        float n3 = fmaxf(fminf(mn1, mx2), fmaxf(m3, o3));
        m1 = n1; m2 = n2; m3 = n3;
    }
    const float gs  = m1 + m2;
    const float m23 = m2 - m3;
    const int   g   = lane >> 2;

    int rank = 0;
    #pragma unroll
    for (int j = 0; j < 8; j++) {
        float gj = __shfl_sync(FULL, gs, j * 4);
        rank += (gj > gs) || (gj == gs && j < g);
    }
    const int selg = (rank < 4);
    if (!selg) {
        #pragma unroll
        for (int i = 0; i < 8; i++) s4[i] = 0.0f;   // reference: score * mask
    }

    float flagmin = CUDART_INF_F;
    if (do_flag) {
        float vsel = selg ? gs : CUDART_INF_F;
        float vuns = selg ? -CUDART_INF_F : gs;
        float mm   = m23;
        #pragma unroll
        for (int d = 16; d; d >>= 1) {
            vsel = fminf(vsel, __shfl_xor_sync(FULL, vsel, d));
            vuns = fmaxf(vuns, __shfl_xor_sync(FULL, vuns, d));
            mm   = fminf(mm,   __shfl_xor_sync(FULL, mm,   d));
        }
        flagmin = fminf(vsel - vuns, mm);
    }

    float wsum = 0.0f, my_w = 0.0f, prevv = 0.0f;
    int   my_ix = 0;
    #pragma unroll
    for (int t = 0; t < 8; t++) {
        float bv = s4[0]; int bp = 0;
        #pragma unroll
        for (int i = 1; i < 8; i++)
            if (s4[i] > bv) { bv = s4[i]; bp = i; }
        float v  = bv;
        int   ix = lane * 8 + bp;
        #pragma unroll
        for (int d = 16; d; d >>= 1) {
            float ov = __shfl_xor_sync(FULL, v, d);
            int   oi = __shfl_xor_sync(FULL, ix, d);
            if (ov > v || (ov == v && oi < ix)) { v = ov; ix = oi; }
        }
        if (t > 0) flagmin = fminf(flagmin, prevv - v);
        prevv = v;
        const int opos  = ix & 7;
        const int olane = ix >> 3;
        #pragma unroll
        for (int i = 0; i < 8; i++)
            if (lane == olane && i == opos) s4[i] = -CUDART_INF_F;
        float cand = sc[0];
        #pragma unroll
        for (int i = 1; i < 8; i++)
            if (i == opos) cand = sc[i];
        float w = __shfl_sync(FULL, cand, olane);
        wsum += w;
        if (lane == t) { my_w = w; my_ix = ix; }
    }

    if (do_flag) {
        float bv = s4[0];
        #pragma unroll
        for (int i = 1; i < 8; i++) bv = fmaxf(bv, s4[i]);
        #pragma unroll
        for (int d = 16; d; d >>= 1)
            bv = fmaxf(bv, __shfl_xor_sync(FULL, bv, d));
        flagmin = fminf(flagmin, prevv - bv);
        if (lane == 0 && flagmin < TAU) {
            int p = atomicAdd(&g_nflag, 1);
            g_flagged[p] = token;
        }
    }

    const float scale = 2.5f / (wsum + 1e-20f);
    if (lane < TOPK) {
        out[(size_t)token * TOPK + lane] = my_w * scale;
        if (write_idx)
            out[(size_t)TOKENS * TOPK + (size_t)token * TOPK + lane] = (float)my_ix;
    }
}

// ---------------------------------------------------------------------------
__global__ __launch_bounds__(256)
void routing_kernel(const float* __restrict__ bias, float* __restrict__ out,
                    int write_idx)
{
    const int lane  = threadIdx.x & 31;
    const int warp  = threadIdx.x >> 5;
    const int token = blockIdx.x * 8 + warp;
    route_one(g_logits + (size_t)token * NEXP, bias, out, write_idx, token,
              lane, 1);
}

// ---------------------------------------------------------------------------
__global__ __launch_bounds__(256)
void recompute_kernel(const float* __restrict__ A, const float* __restrict__ W,
                      const float* __restrict__ bias, float* __restrict__ out,
                      int write_idx)
{
    __shared__ __align__(16) float srow[HIDDEN];
    __shared__ __align__(16) float slog[NEXP];

    const int nf   = g_nflag;
    const int wid  = threadIdx.x >> 5;
    const int lane = threadIdx.x & 31;

    for (int it = blockIdx.x; it < nf; it += gridDim.x) {
        const int token = g_flagged[it];
        for (int i = threadIdx.x * 4; i < HIDDEN; i += 1024)
            *(float4*)(srow + i) = *(const float4*)(A + (size_t)token * HIDDEN + i);
        __syncthreads();

        for (int e = wid * 32; e < wid * 32 + 32; e++) {
            const float* wr = W + (size_t)e * HIDDEN;
            float a0 = 0.f, a1 = 0.f;
            for (int i = lane * 4; i < HIDDEN; i += 256) {
                float4 wv = *(const float4*)(wr + i);
                float4 av = *(const float4*)(srow + i);
                a0 += av.x * wv.x + av.y * wv.y + av.z * wv.z + av.w * wv.w;
                float4 wv2 = *(const float4*)(wr + i + 128);
                float4 av2 = *(const float4*)(srow + i + 128);
                a1 += av2.x * wv2.x + av2.y * wv2.y + av2.z * wv2.z + av2.w * wv2.w;
            }
            float acc = a0 + a1;
            #pragma unroll
            for (int d = 16; d; d >>= 1)
                acc += __shfl_xor_sync(0xffffffffu, acc, d);
            if (lane == 0) slog[e] = acc;
        }
        __syncthreads();

        if (wid == 0)
            route_one(slog, bias, out, write_idx, token, lane, 0);
        __syncthreads();
    }
}

// ---------------------------------------------------------------------------
extern "C" void kernel_launch(void* const* d_in, const int* in_sizes, int n_in,
                              void* d_out, int out_size)
{
    const float* hs   = (const float*)d_in[0];  // [16384, 7168]
    const float* w    = (const float*)d_in[1];  // [256, 7168]
    const float* bias = (const float*)d_in[2];  // [256]
    float* out = (float*)d_out;

    cudaFuncSetAttribute(gemm_f32x2,
                         cudaFuncAttributeMaxDynamicSharedMemorySize,
                         SMEM_TOTAL);

    convert_b_kernel<<<NCH, 256>>>(w);
    gemm_f32x2<<<TOKENS / 128, 256, SMEM_TOTAL>>>(hs);

    const int write_idx = (out_size >= TOKENS * TOPK * 2) ? 1 : 0;
    routing_kernel<<<TOKENS / 8, 256>>>(bias, out, write_idx);
    recompute_kernel<<<128, 256>>>(hs, w, bias, out, write_idx);
}

// round 7
// speedup vs baseline: 1.9136x; 1.9136x over previous
#include <cuda_runtime.h>
#include <cuda_bf16.h>
#include <math_constants.h>
#include <math.h>
#include <cstdint>

#define TOKENS 16384
#define HIDDEN 7168
#define NEXP   256
#define TOPK   8
#define KC     32
#define NCH    (HIDDEN / KC)   // 224
#define TAU    1e-4f

// SMEM per stage: Ah 8K | Al 8K | Bh 16K | Bl 16K = 48KB
#define ST_BYTES 49152
#define OFF_AH   0
#define OFF_AL   8192
#define OFF_BH   16384
#define OFF_BL   32768
#define SMEM_TOTAL (2 * ST_BYTES)

// chunk-blocked swizzle-baked bf16 weights: [ch][n][64B]
__device__ uint32_t g_Bh[(size_t)NEXP * HIDDEN / 2];
__device__ uint32_t g_Bl[(size_t)NEXP * HIDDEN / 2];
__device__ float    g_logits[(size_t)TOKENS * NEXP];
__device__ int      g_nflag;
__device__ int      g_flagged[TOKENS];

__device__ __forceinline__ uint32_t pack_bf2(float lo, float hi) {
    __nv_bfloat162 t = __floats2bfloat162_rn(lo, hi);   // x=lo(low), y=hi(high)
    return *reinterpret_cast<uint32_t*>(&t);
}

#define CPA16(dst, src) \
    asm volatile("cp.async.cg.shared.global [%0], [%1], 16;" \
                 :: "r"(dst), "l"(src) : "memory")

#define LDSM4(r, addr) \
    asm volatile("ldmatrix.sync.aligned.m8n8.x4.shared.b16 {%0,%1,%2,%3}, [%4];" \
                 : "=r"((r)[0]), "=r"((r)[1]), "=r"((r)[2]), "=r"((r)[3]) \
                 : "r"(addr))

#define MMA_BF16(cp, a, B0, B1) \
    asm volatile("mma.sync.aligned.m16n8k16.row.col.f32.bf16.bf16.f32 " \
                 "{%0,%1,%2,%3},{%4,%5,%6,%7},{%8,%9},{%0,%1,%2,%3};" \
                 : "+f"((cp)[0]), "+f"((cp)[1]), "+f"((cp)[2]), "+f"((cp)[3]) \
                 : "r"((a)[0]), "r"((a)[1]), "r"((a)[2]), "r"((a)[3]), \
                   "r"(B0), "r"(B1))

// ---------------------------------------------------------------------------
// Kernel 0: split W fp32 -> bf16 hi/lo, chunk-blocked + swizzle baked.
// Per chunk: row n is 64B; 16B seg s (k 8s..8s+7) stored at seg s^((n>>1)&3).
// ---------------------------------------------------------------------------
__global__ __launch_bounds__(256)
void convert_b_kernel(const float* __restrict__ W) {
    if (blockIdx.x == 0 && threadIdx.x == 0) g_nflag = 0;

    const int ch = blockIdx.x;
    const int n  = threadIdx.x;
    const float* src = W + (size_t)n * HIDDEN + ch * KC;

    float v[32];
    #pragma unroll
    for (int j = 0; j < 8; j++) {
        float4 t = *(const float4*)(src + 4 * j);
        v[4 * j] = t.x; v[4 * j + 1] = t.y; v[4 * j + 2] = t.z; v[4 * j + 3] = t.w;
    }
    uint32_t hw[16], lw[16];
    #pragma unroll
    for (int k = 0; k < 16; k++) {
        float a0 = v[2 * k], a1 = v[2 * k + 1];
        __nv_bfloat16 h0 = __float2bfloat16_rn(a0);
        __nv_bfloat16 h1 = __float2bfloat16_rn(a1);
        hw[k] = pack_bf2(__bfloat162float(h0), __bfloat162float(h1));
        lw[k] = pack_bf2(a0 - __bfloat162float(h0), a1 - __bfloat162float(h1));
    }
    char* dh = (char*)g_Bh + (size_t)ch * (NEXP * 64) + n * 64;
    char* dl = (char*)g_Bl + (size_t)ch * (NEXP * 64) + n * 64;
    const int swn = (n >> 1) & 3;
    #pragma unroll
    for (int s = 0; s < 4; s++) {
        const int so = (s ^ swn) * 16;
        *(uint4*)(dh + so) = make_uint4(hw[4*s], hw[4*s+1], hw[4*s+2], hw[4*s+3]);
        *(uint4*)(dl + so) = make_uint4(lw[4*s], lw[4*s+1], lw[4*s+2], lw[4*s+3]);
    }
}

// ---------------------------------------------------------------------------
// Kernel 1: 3-term bf16-split GEMM via mma.sync.m16n8k16.
// CTA = 128 tokens x 256 experts (grid 128, single wave), 8 warps 2x4,
// warp tile 64x64. logits = Ah*Bh + Al*Bh + Ah*Bl, fp32 accum.
// ---------------------------------------------------------------------------
__global__ __launch_bounds__(256, 1)
void gemm_bf16(const float* __restrict__ A)
{
    extern __shared__ char smem[];
    uint32_t sb;
    asm("{ .reg .u64 t; cvta.to.shared.u64 t, %1; cvt.u32.u64 %0, t; }"
        : "=r"(sb) : "l"((void*)smem));

    const int tid  = threadIdx.x;
    const int lane = tid & 31;
    const int wid  = tid >> 5;
    const int wm   = wid >> 2;          // 0..1
    const int wn   = wid & 3;           // 0..3
    const int bm   = blockIdx.x * 128;

    // ldmatrix lane address components
    const int rowin = ((lane >> 3) & 1) * 8 + (lane & 7);
    const int kqa   = lane >> 4;                 // 0/1: k-octet select (A)
    const int swa   = (rowin >> 1) & 3;
    const int nin   = ((lane >> 4) & 1) * 8 + (lane & 7);
    const int kqb   = (lane >> 3) & 1;           // 0/1: k-octet select (B)
    const int swb   = (nin >> 1) & 3;
    const uint32_t arowoff = (uint32_t)(wm * 64 + rowin) * 64;
    const uint32_t browoff = (uint32_t)(wn * 64 + nin) * 64;

    // A loader: 2 threads/row, 16 k each
    const int arow  = tid >> 1;
    const int apart = tid & 1;
    const int swr   = (arow >> 1) & 3;
    const float* Agp = A + (size_t)(bm + arow) * HIDDEN + apart * 16;

    float cc[4][8][4];
    #pragma unroll
    for (int i = 0; i < 4; i++)
        #pragma unroll
        for (int j = 0; j < 8; j++)
            #pragma unroll
            for (int q = 0; q < 4; q++) cc[i][j][q] = 0.0f;

#define LOAD_B_ASYNC(nc, st) do {                                              \
        const char* __sh = (const char*)g_Bh + (size_t)(nc) * (NEXP * 64)      \
                           + tid * 64;                                         \
        const char* __sl = (const char*)g_Bl + (size_t)(nc) * (NEXP * 64)      \
                           + tid * 64;                                         \
        uint32_t __dh = sb + (st) * ST_BYTES + OFF_BH + tid * 64;              \
        uint32_t __dl = sb + (st) * ST_BYTES + OFF_BL + tid * 64;              \
        _Pragma("unroll")                                                      \
        for (int g = 0; g < 4; g++) {                                          \
            CPA16(__dh + g * 16, __sh + g * 16);                               \
            CPA16(__dl + g * 16, __sl + g * 16);                               \
        }                                                                      \
        asm volatile("cp.async.commit_group;" ::: "memory");                   \
    } while (0)

#define LOAD_A_LDG(nc, va) do {                                                \
        const float* __p = Agp + (size_t)(nc) * KC;                            \
        _Pragma("unroll")                                                      \
        for (int j = 0; j < 4; j++) {                                          \
            float4 t = __ldg((const float4*)(__p + 4 * j));                    \
            (va)[4*j] = t.x; (va)[4*j+1] = t.y;                                \
            (va)[4*j+2] = t.z; (va)[4*j+3] = t.w;                              \
        }                                                                      \
    } while (0)

#define STORE_A(st, va) do {                                                   \
        uint32_t h[8], l[8];                                                   \
        _Pragma("unroll")                                                      \
        for (int k = 0; k < 8; k++) {                                          \
            float a0 = (va)[2*k], a1 = (va)[2*k+1];                            \
            __nv_bfloat16 h0 = __float2bfloat16_rn(a0);                        \
            __nv_bfloat16 h1 = __float2bfloat16_rn(a1);                        \
            h[k] = pack_bf2(__bfloat162float(h0), __bfloat162float(h1));       \
            l[k] = pack_bf2(a0 - __bfloat162float(h0),                         \
                            a1 - __bfloat162float(h1));                        \
        }                                                                      \
        const uint32_t __ab = sb + (st) * ST_BYTES + arow * 64;                \
        const uint32_t s0 = ((2 * apart)     ^ swr) * 16;                      \
        const uint32_t s1 = ((2 * apart + 1) ^ swr) * 16;                      \
        *(uint4*)(smem + (__ab - sb) + OFF_AH + s0) = make_uint4(h[0],h[1],h[2],h[3]); \
        *(uint4*)(smem + (__ab - sb) + OFF_AH + s1) = make_uint4(h[4],h[5],h[6],h[7]); \
        *(uint4*)(smem + (__ab - sb) + OFF_AL + s0) = make_uint4(l[0],l[1],l[2],l[3]); \
        *(uint4*)(smem + (__ab - sb) + OFF_AL + s1) = make_uint4(l[4],l[5],l[6],l[7]); \
    } while (0)

    // ---- prologue ----
    {
        LOAD_B_ASYNC(0, 0);
        float va[16];
        LOAD_A_LDG(0, va);
        STORE_A(0, va);
        asm volatile("cp.async.wait_group 0;" ::: "memory");
        __syncthreads();
    }

    // ---- main loop ----
    for (int c = 0; c < NCH; c++) {
        const int s   = c & 1;
        const bool np = (c + 1 < NCH);
        float va[16];
        if (np) {
            LOAD_B_ASYNC(c + 1, s ^ 1);
            LOAD_A_LDG(c + 1, va);
        }

        const uint32_t base = sb + s * ST_BYTES;
        #pragma unroll
        for (int H = 0; H < 2; H++) {
            const uint32_t aseg = (uint32_t)((((H << 1) | kqa) ^ swa) * 16);
            const uint32_t bseg = (uint32_t)((((H << 1) | kqb) ^ swb) * 16);
            uint32_t ah[4][4], al[4][4], bf[4][4];
            #pragma unroll
            for (int mb = 0; mb < 4; mb++)
                LDSM4(ah[mb], base + OFF_AH + arowoff + mb * 1024 + aseg);
            #pragma unroll
            for (int pr = 0; pr < 4; pr++)
                LDSM4(bf[pr], base + OFF_BH + browoff + pr * 1024 + bseg);
            #pragma unroll
            for (int mb = 0; mb < 4; mb++)
                #pragma unroll
                for (int pr = 0; pr < 4; pr++) {
                    MMA_BF16(cc[mb][2*pr],     ah[mb], bf[pr][0], bf[pr][1]);
                    MMA_BF16(cc[mb][2*pr + 1], ah[mb], bf[pr][2], bf[pr][3]);
                }
            #pragma unroll
            for (int mb = 0; mb < 4; mb++)
                LDSM4(al[mb], base + OFF_AL + arowoff + mb * 1024 + aseg);
            #pragma unroll
            for (int mb = 0; mb < 4; mb++)
                #pragma unroll
                for (int pr = 0; pr < 4; pr++) {
                    MMA_BF16(cc[mb][2*pr],     al[mb], bf[pr][0], bf[pr][1]);
                    MMA_BF16(cc[mb][2*pr + 1], al[mb], bf[pr][2], bf[pr][3]);
                }
            #pragma unroll
            for (int pr = 0; pr < 4; pr++)
                LDSM4(bf[pr], base + OFF_BL + browoff + pr * 1024 + bseg);
            #pragma unroll
            for (int mb = 0; mb < 4; mb++)
                #pragma unroll
                for (int pr = 0; pr < 4; pr++) {
                    MMA_BF16(cc[mb][2*pr],     ah[mb], bf[pr][0], bf[pr][1]);
                    MMA_BF16(cc[mb][2*pr + 1], ah[mb], bf[pr][2], bf[pr][3]);
                }
        }

        if (np) {
            STORE_A(s ^ 1, va);
            asm volatile("cp.async.wait_group 0;" ::: "memory");
        }
        __syncthreads();
    }

    // ---- epilogue ----
    const int lq = lane >> 2;
    const int lr = lane & 3;
    #pragma unroll
    for (int mb = 0; mb < 4; mb++) {
        const int r0 = bm + wm * 64 + mb * 16 + lq;
        #pragma unroll
        for (int nb = 0; nb < 8; nb++) {
            const int col = wn * 64 + nb * 8 + 2 * lr;
            *(float2*)(g_logits + (size_t)r0 * NEXP + col) =
                make_float2(cc[mb][nb][0], cc[mb][nb][1]);
            *(float2*)(g_logits + (size_t)(r0 + 8) * NEXP + col) =
                make_float2(cc[mb][nb][2], cc[mb][nb][3]);
        }
    }
}

// ---------------------------------------------------------------------------
// route_one: reference-exact routing for one token (validated R4-R6).
// ---------------------------------------------------------------------------
__device__ __forceinline__ void route_one(const float* __restrict__ row,
                                          const float* __restrict__ bias,
                                          float* __restrict__ out,
                                          int write_idx, int token, int lane,
                                          int do_flag)
{
    const unsigned FULL = 0xffffffffu;

    float4 l0 = *(const float4*)(row + lane * 8);
    float4 l1 = *(const float4*)(row + lane * 8 + 4);
    float4 b0 = *(const float4*)(bias + lane * 8);
    float4 b1 = *(const float4*)(bias + lane * 8 + 4);

    float lv[8] = {l0.x, l0.y, l0.z, l0.w, l1.x, l1.y, l1.z, l1.w};
    float bb[8] = {b0.x, b0.y, b0.z, b0.w, b1.x, b1.y, b1.z, b1.w};
    float sc[8], s4[8];
    #pragma unroll
    for (int i = 0; i < 8; i++) {
        float s = 1.0f / (1.0f + expf(-lv[i]));
        sc[i] = s;
        s4[i] = s + bb[i];
    }

    float m1 = -CUDART_INF_F, m2 = -CUDART_INF_F, m3 = -CUDART_INF_F;
    #pragma unroll
    for (int i = 0; i < 8; i++) {
        float v = s4[i];
        if (v > m1)      { m3 = m2; m2 = m1; m1 = v; }
        else if (v > m2) { m3 = m2; m2 = v; }
        else if (v > m3) { m3 = v; }
    }
    #pragma unroll
    for (int d = 1; d <= 2; d <<= 1) {
        float o1 = __shfl_xor_sync(FULL, m1, d);
        float o2 = __shfl_xor_sync(FULL, m2, d);
        float o3 = __shfl_xor_sync(FULL, m3, d);
        float mn1 = fminf(m1, o1);
        float mx2 = fmaxf(m2, o2);
        float n1 = fmaxf(m1, o1);
        float n2 = fmaxf(mn1, mx2);
        float n3 = fmaxf(fminf(mn1, mx2), fmaxf(m3, o3));
        m1 = n1; m2 = n2; m3 = n3;
    }
    const float gs  = m1 + m2;
    const float m23 = m2 - m3;
    const int   g   = lane >> 2;

    int rank = 0;
    #pragma unroll
    for (int j = 0; j < 8; j++) {
        float gj = __shfl_sync(FULL, gs, j * 4);
        rank += (gj > gs) || (gj == gs && j < g);
    }
    const int selg = (rank < 4);
    if (!selg) {
        #pragma unroll
        for (int i = 0; i < 8; i++) s4[i] = 0.0f;   // reference: score * mask
    }

    float flagmin = CUDART_INF_F;
    if (do_flag) {
        float vsel = selg ? gs : CUDART_INF_F;
        float vuns = selg ? -CUDART_INF_F : gs;
        float mm   = m23;
        #pragma unroll
        for (int d = 16; d; d >>= 1) {
            vsel = fminf(vsel, __shfl_xor_sync(FULL, vsel, d));
            vuns = fmaxf(vuns, __shfl_xor_sync(FULL, vuns, d));
            mm   = fminf(mm,   __shfl_xor_sync(FULL, mm,   d));
        }
        flagmin = fminf(vsel - vuns, mm);
    }

    float wsum = 0.0f, my_w = 0.0f, prevv = 0.0f;
    int   my_ix = 0;
    #pragma unroll
    for (int t = 0; t < 8; t++) {
        float bv = s4[0]; int bp = 0;
        #pragma unroll
        for (int i = 1; i < 8; i++)
            if (s4[i] > bv) { bv = s4[i]; bp = i; }
        float v  = bv;
        int   ix = lane * 8 + bp;
        #pragma unroll
        for (int d = 16; d; d >>= 1) {
            float ov = __shfl_xor_sync(FULL, v, d);
            int   oi = __shfl_xor_sync(FULL, ix, d);
            if (ov > v || (ov == v && oi < ix)) { v = ov; ix = oi; }
        }
        if (t > 0) flagmin = fminf(flagmin, prevv - v);
        prevv = v;
        const int opos  = ix & 7;
        const int olane = ix >> 3;
        #pragma unroll
        for (int i = 0; i < 8; i++)
            if (lane == olane && i == opos) s4[i] = -CUDART_INF_F;
        float cand = sc[0];
        #pragma unroll
        for (int i = 1; i < 8; i++)
            if (i == opos) cand = sc[i];
        float w = __shfl_sync(FULL, cand, olane);
        wsum += w;
        if (lane == t) { my_w = w; my_ix = ix; }
    }

    if (do_flag) {
        float bv = s4[0];
        #pragma unroll
        for (int i = 1; i < 8; i++) bv = fmaxf(bv, s4[i]);
        #pragma unroll
        for (int d = 16; d; d >>= 1)
            bv = fmaxf(bv, __shfl_xor_sync(FULL, bv, d));
        flagmin = fminf(flagmin, prevv - bv);
        if (lane == 0 && flagmin < TAU) {
            int p = atomicAdd(&g_nflag, 1);
            g_flagged[p] = token;
        }
    }

    const float scale = 2.5f / (wsum + 1e-20f);
    if (lane < TOPK) {
        out[(size_t)token * TOPK + lane] = my_w * scale;
        if (write_idx)
            out[(size_t)TOKENS * TOPK + (size_t)token * TOPK + lane] = (float)my_ix;
    }
}

// ---------------------------------------------------------------------------
__global__ __launch_bounds__(256)
void routing_kernel(const float* __restrict__ bias, float* __restrict__ out,
                    int write_idx)
{
    const int lane  = threadIdx.x & 31;
    const int warp  = threadIdx.x >> 5;
    const int token = blockIdx.x * 8 + warp;
    route_one(g_logits + (size_t)token * NEXP, bias, out, write_idx, token,
              lane, 1);
}

// ---------------------------------------------------------------------------
__global__ __launch_bounds__(256)
void recompute_kernel(const float* __restrict__ A, const float* __restrict__ W,
                      const float* __restrict__ bias, float* __restrict__ out,
                      int write_idx)
{
    __shared__ __align__(16) float srow[HIDDEN];
    __shared__ __align__(16) float slog[NEXP];

    const int nf   = g_nflag;
    const int wid  = threadIdx.x >> 5;
    const int lane = threadIdx.x & 31;

    for (int it = blockIdx.x; it < nf; it += gridDim.x) {
        const int token = g_flagged[it];
        for (int i = threadIdx.x * 4; i < HIDDEN; i += 1024)
            *(float4*)(srow + i) = *(const float4*)(A + (size_t)token * HIDDEN + i);
        __syncthreads();

        for (int e = wid * 32; e < wid * 32 + 32; e++) {
            const float* wr = W + (size_t)e * HIDDEN;
            float a0 = 0.f, a1 = 0.f;
            for (int i = lane * 4; i < HIDDEN; i += 256) {
                float4 wv = *(const float4*)(wr + i);
                float4 av = *(const float4*)(srow + i);
                a0 += av.x * wv.x + av.y * wv.y + av.z * wv.z + av.w * wv.w;
                float4 wv2 = *(const float4*)(wr + i + 128);
                float4 av2 = *(const float4*)(srow + i + 128);
                a1 += av2.x * wv2.x + av2.y * wv2.y + av2.z * wv2.z + av2.w * wv2.w;
            }
            float acc = a0 + a1;
            #pragma unroll
            for (int d = 16; d; d >>= 1)
                acc += __shfl_xor_sync(0xffffffffu, acc, d);
            if (lane == 0) slog[e] = acc;
        }
        __syncthreads();

        if (wid == 0)
            route_one(slog, bias, out, write_idx, token, lane, 0);
        __syncthreads();
    }
}

// ---------------------------------------------------------------------------
extern "C" void kernel_launch(void* const* d_in, const int* in_sizes, int n_in,
                              void* d_out, int out_size)
{
    const float* hs   = (const float*)d_in[0];  // [16384, 7168]
    const float* w    = (const float*)d_in[1];  // [256, 7168]
    const float* bias = (const float*)d_in[2];  // [256]
    float* out = (float*)d_out;

    cudaFuncSetAttribute(gemm_bf16,
                         cudaFuncAttributeMaxDynamicSharedMemorySize,
                         SMEM_TOTAL);

    convert_b_kernel<<<NCH, 256>>>(w);
    gemm_bf16<<<TOKENS / 128, 256, SMEM_TOTAL>>>(hs);

    const int write_idx = (out_size >= TOKENS * TOPK * 2) ? 1 : 0;
    routing_kernel<<<TOKENS / 8, 256>>>(bias, out, write_idx);
    recompute_kernel<<<128, 256>>>(hs, w, bias, out, write_idx);
}